// round 2
// baseline (speedup 1.0000x reference)
#include <cuda_runtime.h>
#include <cuda_bf16.h>
#include <math.h>

// ---------------- static scratch (no allocs allowed) ----------------
#define NMAX 50176
#define EMAX 1700000
#define SCAN_B 512

__device__ float g_h1 [NMAX * 256];   // x @ W1
__device__ float g_h1a[NMAX * 256];   // layer1 output (post softmax-agg + bias + ELU)
__device__ float g_h2 [NMAX * 40];    // h1a @ W2
__device__ float g_as1[NMAX * 4], g_ad1[NMAX * 4];
__device__ float g_as2[NMAX],     g_ad2[NMAX];
__device__ int   g_deg[NMAX], g_off[NMAX + 1], g_cur[NMAX];
__device__ int   g_bsum[256], g_boff[256];
__device__ int   g_csr[EMAX];
__device__ int   g_is64;

// ---------------- edge dtype detection ----------------
// Reference declares int64 but JAX default config downcasts to int32.
// For int64 little-endian data with values < 2^31, odd int32 words are 0.
// For int32 data they are random node ids in [0, N). Sample 64 of them.
__global__ void k_detect(const int* __restrict__ e32, int E) {
    if (threadIdx.x == 0 && blockIdx.x == 0) {
        int is64 = 1;
        int nchk = (E < 64) ? E : 64;
        for (int i = 0; i < nchk; i++) {
            if (e32[2 * i + 1] != 0) { is64 = 0; break; }
        }
        g_is64 = is64;
    }
}

__device__ __forceinline__ int edge_at(const void* edge, int is64, long long idx) {
    if (is64) return (int)((const long long*)edge)[idx];
    return ((const int*)edge)[idx];
}

// ---------------- CSR build ----------------
__global__ void k_zero_deg(int N) {
    int i = blockIdx.x * blockDim.x + threadIdx.x;
    if (i < N) g_deg[i] = 0;
}

__global__ void k_count(const void* __restrict__ edge, int E, int N) {
    int e = blockIdx.x * blockDim.x + threadIdx.x;
    int ET = E + N;
    if (e >= ET) return;
    int is64 = g_is64;
    int dst = (e < E) ? edge_at(edge, is64, (long long)E + e) : (e - E);
    atomicAdd(&g_deg[dst], 1);
}

__global__ void k_scan1(int N) {
    __shared__ int s[SCAN_B];
    int i = blockIdx.x * SCAN_B + threadIdx.x;
    s[threadIdx.x] = (i < N) ? g_deg[i] : 0;
    __syncthreads();
    for (int o = SCAN_B / 2; o > 0; o >>= 1) {
        if (threadIdx.x < o) s[threadIdx.x] += s[threadIdx.x + o];
        __syncthreads();
    }
    if (threadIdx.x == 0) g_bsum[blockIdx.x] = s[0];
}

__global__ void k_scan2(int nb, int N) {
    if (threadIdx.x == 0 && blockIdx.x == 0) {
        int run = 0;
        for (int b = 0; b < nb; b++) { g_boff[b] = run; run += g_bsum[b]; }
        g_off[N] = run;
    }
}

__global__ void k_scan3(int N) {
    __shared__ int s[SCAN_B];
    int i = blockIdx.x * SCAN_B + threadIdx.x;
    int v = (i < N) ? g_deg[i] : 0;
    s[threadIdx.x] = v;
    __syncthreads();
    for (int o = 1; o < SCAN_B; o <<= 1) {
        int t = (threadIdx.x >= o) ? s[threadIdx.x - o] : 0;
        __syncthreads();
        s[threadIdx.x] += t;
        __syncthreads();
    }
    if (i < N) {
        int ex = g_boff[blockIdx.x] + s[threadIdx.x] - v;
        g_off[i] = ex;
        g_cur[i] = ex;
    }
}

__global__ void k_scatter(const void* __restrict__ edge, int E, int N) {
    int e = blockIdx.x * blockDim.x + threadIdx.x;
    int ET = E + N;
    if (e >= ET) return;
    int src, dst;
    if (e < E) {
        int is64 = g_is64;
        src = edge_at(edge, is64, e);
        dst = edge_at(edge, is64, (long long)E + e);
    } else {
        src = dst = e - E;
    }
    int pos = atomicAdd(&g_cur[dst], 1);
    g_csr[pos] = src;
}

// ---------------- GEMM1: h1 = x @ W1  (M x 256 x 256) ----------------
#define BM 64
#define BN 64
#define BK 16
__global__ void k_gemm1(const float* __restrict__ X, const float* __restrict__ W, int M) {
    __shared__ float As[BK][BM];
    __shared__ float Bs[BK][BN];
    int tid = threadIdx.x;               // 256 threads
    int tx = tid & 15, ty = tid >> 4;
    int row0 = blockIdx.y * BM;
    int col0 = blockIdx.x * BN;
    float c[4][4];
#pragma unroll
    for (int i = 0; i < 4; i++)
#pragma unroll
        for (int j = 0; j < 4; j++) c[i][j] = 0.f;

    int arow = tid >> 2;            // 0..63
    int acol = (tid & 3) * 4;       // 0,4,8,12
    int brow = tid >> 4;            // 0..15
    int bcol = (tid & 15) * 4;      // 0..60

    for (int kt = 0; kt < 256; kt += BK) {
        float4 av = make_float4(0.f, 0.f, 0.f, 0.f);
        int gr = row0 + arow;
        if (gr < M) av = *(const float4*)&X[(size_t)gr * 256 + kt + acol];
        As[acol + 0][arow] = av.x;
        As[acol + 1][arow] = av.y;
        As[acol + 2][arow] = av.z;
        As[acol + 3][arow] = av.w;
        float4 bv = *(const float4*)&W[(size_t)(kt + brow) * 256 + col0 + bcol];
        *(float4*)&Bs[brow][bcol] = bv;
        __syncthreads();
#pragma unroll
        for (int kk = 0; kk < BK; kk++) {
            float4 a4 = *(const float4*)&As[kk][ty * 4];
            float4 b4 = *(const float4*)&Bs[kk][tx * 4];
            float a[4] = {a4.x, a4.y, a4.z, a4.w};
            float b[4] = {b4.x, b4.y, b4.z, b4.w};
#pragma unroll
            for (int i = 0; i < 4; i++)
#pragma unroll
                for (int j = 0; j < 4; j++) c[i][j] = fmaf(a[i], b[j], c[i][j]);
        }
        __syncthreads();
    }
#pragma unroll
    for (int i = 0; i < 4; i++) {
        int gr = row0 + ty * 4 + i;
        if (gr < M) {
            float4 v = make_float4(c[i][0], c[i][1], c[i][2], c[i][3]);
            *(float4*)&g_h1[(size_t)gr * 256 + col0 + tx * 4] = v;
        }
    }
}

// ---------------- attn1: a_src/a_dst per node per head (warp/node) ----------------
__global__ void k_attn1(const float* __restrict__ att_s, const float* __restrict__ att_d, int M) {
    int w = (blockIdx.x * blockDim.x + threadIdx.x) >> 5;
    int lane = threadIdx.x & 31;
    if (w >= M) return;
    int c0 = lane * 8;                       // lane owns channels [c0, c0+8) -> one head
    const float4* hp = (const float4*)&g_h1[(size_t)w * 256 + c0];
    float4 h0 = hp[0], h1v = hp[1];
    const float4* sp = (const float4*)&att_s[c0];
    const float4* dp = (const float4*)&att_d[c0];
    float4 s0 = sp[0], s1 = sp[1];
    float4 d0 = dp[0], d1 = dp[1];
    float ps = h0.x*s0.x + h0.y*s0.y + h0.z*s0.z + h0.w*s0.w
             + h1v.x*s1.x + h1v.y*s1.y + h1v.z*s1.z + h1v.w*s1.w;
    float pd = h0.x*d0.x + h0.y*d0.y + h0.z*d0.z + h0.w*d0.w
             + h1v.x*d1.x + h1v.y*d1.y + h1v.z*d1.z + h1v.w*d1.w;
#pragma unroll
    for (int o = 4; o >= 1; o >>= 1) {       // reduce within 8-lane head group
        ps += __shfl_xor_sync(0xffffffffu, ps, o);
        pd += __shfl_xor_sync(0xffffffffu, pd, o);
    }
    if ((lane & 7) == 0) {
        int hh = lane >> 3;
        g_as1[w * 4 + hh] = ps;
        g_ad1[w * 4 + hh] = pd;
    }
}

// ---------------- agg1: segment softmax + weighted sum, + bias + ELU ----------------
__global__ void k_agg1(const float* __restrict__ bias, int M) {
    int w = (blockIdx.x * blockDim.x + threadIdx.x) >> 5;
    int lane = threadIdx.x & 31;
    if (w >= M) return;
    int start = g_off[w], end = g_off[w + 1];
    float4 ad = *(const float4*)&g_ad1[w * 4];

    float m0 = -1e30f, m1 = -1e30f, m2 = -1e30f, m3 = -1e30f;
    for (int j = start + lane; j < end; j += 32) {
        int s = g_csr[j];
        float4 as = *(const float4*)&g_as1[s * 4];
        float e0 = as.x + ad.x; e0 = e0 > 0.f ? e0 : 0.2f * e0; m0 = fmaxf(m0, e0);
        float e1 = as.y + ad.y; e1 = e1 > 0.f ? e1 : 0.2f * e1; m1 = fmaxf(m1, e1);
        float e2 = as.z + ad.z; e2 = e2 > 0.f ? e2 : 0.2f * e2; m2 = fmaxf(m2, e2);
        float e3 = as.w + ad.w; e3 = e3 > 0.f ? e3 : 0.2f * e3; m3 = fmaxf(m3, e3);
    }
#pragma unroll
    for (int o = 16; o >= 1; o >>= 1) {
        m0 = fmaxf(m0, __shfl_xor_sync(0xffffffffu, m0, o));
        m1 = fmaxf(m1, __shfl_xor_sync(0xffffffffu, m1, o));
        m2 = fmaxf(m2, __shfl_xor_sync(0xffffffffu, m2, o));
        m3 = fmaxf(m3, __shfl_xor_sync(0xffffffffu, m3, o));
    }
    int hh = lane >> 3;
    float mh  = (hh == 0) ? m0   : (hh == 1) ? m1   : (hh == 2) ? m2   : m3;
    float adh = (hh == 0) ? ad.x : (hh == 1) ? ad.y : (hh == 2) ? ad.z : ad.w;

    float acc[8] = {0.f, 0.f, 0.f, 0.f, 0.f, 0.f, 0.f, 0.f};
    float denom = 0.f;
    int c0 = lane * 8;
    for (int j = start; j < end; j++) {
        int s = g_csr[j];
        float e = g_as1[s * 4 + hh] + adh;
        e = e > 0.f ? e : 0.2f * e;
        float wgt = __expf(e - mh);
        denom += wgt;
        const float4* hp = (const float4*)&g_h1[(size_t)s * 256 + c0];
        float4 v0 = hp[0], v1 = hp[1];
        acc[0] = fmaf(wgt, v0.x, acc[0]);
        acc[1] = fmaf(wgt, v0.y, acc[1]);
        acc[2] = fmaf(wgt, v0.z, acc[2]);
        acc[3] = fmaf(wgt, v0.w, acc[3]);
        acc[4] = fmaf(wgt, v1.x, acc[4]);
        acc[5] = fmaf(wgt, v1.y, acc[5]);
        acc[6] = fmaf(wgt, v1.z, acc[6]);
        acc[7] = fmaf(wgt, v1.w, acc[7]);
    }
    float inv = 1.f / denom;
#pragma unroll
    for (int k = 0; k < 8; k++) {
        float v = acc[k] * inv + bias[c0 + k];
        v = v > 0.f ? v : (__expf(v) - 1.f);   // ELU
        g_h1a[(size_t)w * 256 + c0 + k] = v;
    }
}

// ---------------- GEMM2: h2 = h1a @ W2  (M x 256 x 40) ----------------
__global__ void k_gemm2(const float* __restrict__ W2, int M) {
    __shared__ float Ws[256 * 40];
    int tid = threadIdx.x;               // 320 threads
    for (int i = tid; i < 256 * 40; i += 320) Ws[i] = W2[i];
    __syncthreads();
    int r = tid / 40, c = tid % 40;
    int gr = blockIdx.x * 8 + r;
    if (gr >= M) return;
    const float* hrow = &g_h1a[(size_t)gr * 256];
    float a0 = 0.f, a1 = 0.f, a2 = 0.f, a3 = 0.f;
#pragma unroll 4
    for (int k = 0; k < 256; k += 4) {
        a0 = fmaf(__ldg(&hrow[k + 0]), Ws[(k + 0) * 40 + c], a0);
        a1 = fmaf(__ldg(&hrow[k + 1]), Ws[(k + 1) * 40 + c], a1);
        a2 = fmaf(__ldg(&hrow[k + 2]), Ws[(k + 2) * 40 + c], a2);
        a3 = fmaf(__ldg(&hrow[k + 3]), Ws[(k + 3) * 40 + c], a3);
    }
    g_h2[(size_t)gr * 40 + c] = (a0 + a1) + (a2 + a3);
}

// ---------------- attn2 ----------------
__global__ void k_attn2(const float* __restrict__ att_s, const float* __restrict__ att_d, int M) {
    int w = (blockIdx.x * blockDim.x + threadIdx.x) >> 5;
    int lane = threadIdx.x & 31;
    if (w >= M) return;
    const float* h = &g_h2[(size_t)w * 40];
    float ps = h[lane] * __ldg(&att_s[lane]);
    float pd = h[lane] * __ldg(&att_d[lane]);
    if (lane < 8) {
        ps += h[32 + lane] * __ldg(&att_s[32 + lane]);
        pd += h[32 + lane] * __ldg(&att_d[32 + lane]);
    }
#pragma unroll
    for (int o = 16; o >= 1; o >>= 1) {
        ps += __shfl_xor_sync(0xffffffffu, ps, o);
        pd += __shfl_xor_sync(0xffffffffu, pd, o);
    }
    if (lane == 0) { g_as2[w] = ps; g_ad2[w] = pd; }
}

// ---------------- agg2: final output ----------------
__global__ void k_agg2(const float* __restrict__ b2, float* __restrict__ out, int M) {
    int w = (blockIdx.x * blockDim.x + threadIdx.x) >> 5;
    int lane = threadIdx.x & 31;
    if (w >= M) return;
    int start = g_off[w], end = g_off[w + 1];
    float adv = g_ad2[w];
    float m = -1e30f;
    for (int j = start + lane; j < end; j += 32) {
        int s = g_csr[j];
        float e = g_as2[s] + adv;
        e = e > 0.f ? e : 0.2f * e;
        m = fmaxf(m, e);
    }
#pragma unroll
    for (int o = 16; o >= 1; o >>= 1) m = fmaxf(m, __shfl_xor_sync(0xffffffffu, m, o));
    float denom = 0.f, acc0 = 0.f, acc1 = 0.f;
    for (int j = start; j < end; j++) {
        int s = g_csr[j];
        float e = g_as2[s] + adv;
        e = e > 0.f ? e : 0.2f * e;
        float wgt = __expf(e - m);
        denom += wgt;
        acc0 = fmaf(wgt, g_h2[(size_t)s * 40 + lane], acc0);
        if (lane < 8) acc1 = fmaf(wgt, g_h2[(size_t)s * 40 + 32 + lane], acc1);
    }
    float inv = 1.f / denom;
    out[(size_t)w * 40 + lane] = acc0 * inv + __ldg(&b2[lane]);
    if (lane < 8) out[(size_t)w * 40 + 32 + lane] = acc1 * inv + __ldg(&b2[32 + lane]);
}

// ---------------- launch ----------------
extern "C" void kernel_launch(void* const* d_in, const int* in_sizes, int n_in,
                              void* d_out, int out_size) {
    const float* x    = (const float*)d_in[0];
    const void*  edge = (const void*)d_in[1];
    const float* W1   = (const float*)d_in[2];
    const float* as1  = (const float*)d_in[3];
    const float* ad1  = (const float*)d_in[4];
    const float* b1   = (const float*)d_in[5];
    const float* W2   = (const float*)d_in[6];
    const float* as2  = (const float*)d_in[7];
    const float* ad2  = (const float*)d_in[8];
    const float* b2   = (const float*)d_in[9];
    float* out = (float*)d_out;

    int N  = in_sizes[0] / 256;
    int E  = in_sizes[1] / 2;
    int ET = E + N;
    int nb = (N + SCAN_B - 1) / SCAN_B;

    // Edge dtype detection (int64 declared, but JAX default config gives int32)
    k_detect<<<1, 32>>>((const int*)edge, E);

    // CSR build (by destination)
    k_zero_deg<<<(N + 255) / 256, 256>>>(N);
    k_count<<<(ET + 255) / 256, 256>>>(edge, E, N);
    k_scan1<<<nb, SCAN_B>>>(N);
    k_scan2<<<1, 32>>>(nb, N);
    k_scan3<<<nb, SCAN_B>>>(N);
    k_scatter<<<(ET + 255) / 256, 256>>>(edge, E, N);

    // Layer 1
    dim3 g1(256 / BN, (N + BM - 1) / BM);
    k_gemm1<<<g1, 256>>>(x, W1, N);
    int warpGrid = (N * 32 + 255) / 256;
    k_attn1<<<warpGrid, 256>>>(as1, ad1, N);
    k_agg1<<<warpGrid, 256>>>(b1, N);

    // Layer 2
    k_gemm2<<<(N + 7) / 8, 320>>>(W2, N);
    k_attn2<<<warpGrid, 256>>>(as2, ad2, N);
    k_agg2<<<warpGrid, 256>>>(b2, out, N);
}

// round 4
// speedup vs baseline: 1.0921x; 1.0921x over previous
#include <cuda_runtime.h>
#include <cuda_bf16.h>
#include <cstdint>
#include <math.h>

// ---------------- static scratch (no allocs allowed) ----------------
#define NMAX 50176
#define EMAX 1700000
#define SCAN_B 512

__device__ float g_h1 [NMAX * 256];   // x @ W1
__device__ float g_h1a[NMAX * 256];   // layer1 output (post softmax-agg + bias + ELU)
__device__ float g_h2 [NMAX * 40];    // h1a @ W2
__device__ float g_as1[NMAX * 4], g_ad1[NMAX * 4];
__device__ float g_as2[NMAX],     g_ad2[NMAX];
__device__ int   g_deg[NMAX], g_off[NMAX + 1], g_cur[NMAX];
__device__ int   g_bsum[256], g_boff[256];
__device__ int   g_csr[EMAX];
__device__ int   g_is64;
// bf16 split operands for tensor-core GEMM1
__device__ __nv_bfloat16 g_xh[NMAX * 256], g_xl[NMAX * 256];
__device__ __nv_bfloat16 g_wh[256 * 256],  g_wl[256 * 256];

// ---------------- PTX helpers ----------------
__device__ __forceinline__ unsigned smem_u32(const void* p) {
    return (unsigned)__cvta_generic_to_shared(p);
}
__device__ __forceinline__ void ldsm_x4(unsigned addr, unsigned& r0, unsigned& r1, unsigned& r2, unsigned& r3) {
    asm volatile("ldmatrix.sync.aligned.m8n8.x4.shared.b16 {%0,%1,%2,%3},[%4];"
                 : "=r"(r0), "=r"(r1), "=r"(r2), "=r"(r3) : "r"(addr));
}
__device__ __forceinline__ void ldsm_x4t(unsigned addr, unsigned& r0, unsigned& r1, unsigned& r2, unsigned& r3) {
    asm volatile("ldmatrix.sync.aligned.m8n8.x4.trans.shared.b16 {%0,%1,%2,%3},[%4];"
                 : "=r"(r0), "=r"(r1), "=r"(r2), "=r"(r3) : "r"(addr));
}
__device__ __forceinline__ void mma_bf16(float* c, unsigned a0, unsigned a1, unsigned a2, unsigned a3,
                                         unsigned b0, unsigned b1) {
    asm volatile("mma.sync.aligned.m16n8k16.row.col.f32.bf16.bf16.f32 "
                 "{%0,%1,%2,%3},{%4,%5,%6,%7},{%8,%9},{%0,%1,%2,%3};"
                 : "+f"(c[0]), "+f"(c[1]), "+f"(c[2]), "+f"(c[3])
                 : "r"(a0), "r"(a1), "r"(a2), "r"(a3), "r"(b0), "r"(b1));
}

// ---------------- bf16 split conversion ----------------
__global__ void k_split(const float* __restrict__ src, __nv_bfloat16* __restrict__ hi,
                        __nv_bfloat16* __restrict__ lo, int n) {
    int i = blockIdx.x * blockDim.x + threadIdx.x;
    if (i >= n) return;
    float v = src[i];
    __nv_bfloat16 h = __float2bfloat16(v);
    hi[i] = h;
    lo[i] = __float2bfloat16(v - __bfloat162float(h));
}

// ---------------- edge dtype detection ----------------
__global__ void k_detect(const int* __restrict__ e32, int E) {
    if (threadIdx.x == 0 && blockIdx.x == 0) {
        int is64 = 1;
        int nchk = (E < 64) ? E : 64;
        for (int i = 0; i < nchk; i++) {
            if (e32[2 * i + 1] != 0) { is64 = 0; break; }
        }
        g_is64 = is64;
    }
}

__device__ __forceinline__ int edge_at(const void* edge, int is64, long long idx) {
    if (is64) return (int)((const long long*)edge)[idx];
    return ((const int*)edge)[idx];
}

// ---------------- CSR build ----------------
__global__ void k_zero_deg(int N) {
    int i = blockIdx.x * blockDim.x + threadIdx.x;
    if (i < N) g_deg[i] = 0;
}

__global__ void k_count(const void* __restrict__ edge, int E, int N) {
    int e = blockIdx.x * blockDim.x + threadIdx.x;
    int ET = E + N;
    if (e >= ET) return;
    int is64 = g_is64;
    int dst = (e < E) ? edge_at(edge, is64, (long long)E + e) : (e - E);
    atomicAdd(&g_deg[dst], 1);
}

__global__ void k_scan1(int N) {
    __shared__ int s[SCAN_B];
    int i = blockIdx.x * SCAN_B + threadIdx.x;
    s[threadIdx.x] = (i < N) ? g_deg[i] : 0;
    __syncthreads();
    for (int o = SCAN_B / 2; o > 0; o >>= 1) {
        if (threadIdx.x < o) s[threadIdx.x] += s[threadIdx.x + o];
        __syncthreads();
    }
    if (threadIdx.x == 0) g_bsum[blockIdx.x] = s[0];
}

__global__ void k_scan2(int nb, int N) {
    if (threadIdx.x == 0 && blockIdx.x == 0) {
        int run = 0;
        for (int b = 0; b < nb; b++) { g_boff[b] = run; run += g_bsum[b]; }
        g_off[N] = run;
    }
}

__global__ void k_scan3(int N) {
    __shared__ int s[SCAN_B];
    int i = blockIdx.x * SCAN_B + threadIdx.x;
    int v = (i < N) ? g_deg[i] : 0;
    s[threadIdx.x] = v;
    __syncthreads();
    for (int o = 1; o < SCAN_B; o <<= 1) {
        int t = (threadIdx.x >= o) ? s[threadIdx.x - o] : 0;
        __syncthreads();
        s[threadIdx.x] += t;
        __syncthreads();
    }
    if (i < N) {
        int ex = g_boff[blockIdx.x] + s[threadIdx.x] - v;
        g_off[i] = ex;
        g_cur[i] = ex;
    }
}

__global__ void k_scatter(const void* __restrict__ edge, int E, int N) {
    int e = blockIdx.x * blockDim.x + threadIdx.x;
    int ET = E + N;
    if (e >= ET) return;
    int src, dst;
    if (e < E) {
        int is64 = g_is64;
        src = edge_at(edge, is64, e);
        dst = edge_at(edge, is64, (long long)E + e);
    } else {
        src = dst = e - E;
    }
    int pos = atomicAdd(&g_cur[dst], 1);
    g_csr[pos] = src;
}

// ---------------- GEMM1 (tensor core): h1 = x @ W1, 3-way bf16 split ----------------
// block tile 128x64, BK=32, 8 warps in 4(M) x 2(N), warp tile 32x32
#define LDA 40
#define LDB 72
__global__ void __launch_bounds__(256) k_gemm1_tc(int M) {
    __shared__ __nv_bfloat16 Ah[128 * LDA], Al[128 * LDA];
    __shared__ __nv_bfloat16 Bh[32 * LDB],  Bl[32 * LDB];
    int tid = threadIdx.x;
    int warp = tid >> 5, lane = tid & 31;
    int wm = warp & 3, wn = warp >> 2;
    int row0 = blockIdx.y * 128, col0 = blockIdx.x * 64;

    float acc[2][4][4];
#pragma unroll
    for (int mi = 0; mi < 2; mi++)
#pragma unroll
        for (int ni = 0; ni < 4; ni++)
#pragma unroll
            for (int k = 0; k < 4; k++) acc[mi][ni][k] = 0.f;

    int lrow = lane & 15, lcb = lane >> 4;

    for (int kt = 0; kt < 256; kt += 32) {
        // load A tile (128x32) hi+lo
#pragma unroll
        for (int i = 0; i < 2; i++) {
            int v = tid + i * 256;
            int r = v >> 2, cv = (v & 3) * 8;
            int gr = row0 + r;
            uint4 vh, vl;
            if (gr < M) {
                vh = *(const uint4*)&g_xh[(size_t)gr * 256 + kt + cv];
                vl = *(const uint4*)&g_xl[(size_t)gr * 256 + kt + cv];
            } else {
                vh = make_uint4(0u, 0u, 0u, 0u);
                vl = vh;
            }
            *(uint4*)&Ah[r * LDA + cv] = vh;
            *(uint4*)&Al[r * LDA + cv] = vl;
        }
        // load B tile (32x64) hi+lo
        {
            int r = tid >> 3, cv = (tid & 7) * 8;
            *(uint4*)&Bh[r * LDB + cv] = *(const uint4*)&g_wh[(size_t)(kt + r) * 256 + col0 + cv];
            *(uint4*)&Bl[r * LDB + cv] = *(const uint4*)&g_wl[(size_t)(kt + r) * 256 + col0 + cv];
        }
        __syncthreads();

#pragma unroll
        for (int ks = 0; ks < 32; ks += 16) {
            unsigned ah[2][4], al[2][4], bh[2][4], bl[2][4];
#pragma unroll
            for (int mi = 0; mi < 2; mi++) {
                unsigned ad = smem_u32(&Ah[(wm * 32 + mi * 16 + lrow) * LDA + ks + lcb * 8]);
                ldsm_x4(ad, ah[mi][0], ah[mi][1], ah[mi][2], ah[mi][3]);
                unsigned ad2 = smem_u32(&Al[(wm * 32 + mi * 16 + lrow) * LDA + ks + lcb * 8]);
                ldsm_x4(ad2, al[mi][0], al[mi][1], al[mi][2], al[mi][3]);
            }
#pragma unroll
            for (int nj = 0; nj < 2; nj++) {
                unsigned bd = smem_u32(&Bh[(ks + lrow) * LDB + wn * 32 + nj * 16 + lcb * 8]);
                ldsm_x4t(bd, bh[nj][0], bh[nj][1], bh[nj][2], bh[nj][3]);
                unsigned bd2 = smem_u32(&Bl[(ks + lrow) * LDB + wn * 32 + nj * 16 + lcb * 8]);
                ldsm_x4t(bd2, bl[nj][0], bl[nj][1], bl[nj][2], bl[nj][3]);
            }
#pragma unroll
            for (int mi = 0; mi < 2; mi++)
#pragma unroll
                for (int ni = 0; ni < 4; ni++) {
                    int nj = ni >> 1, s2 = (ni & 1) * 2;
                    mma_bf16(acc[mi][ni], ah[mi][0], ah[mi][1], ah[mi][2], ah[mi][3],
                             bh[nj][s2], bh[nj][s2 + 1]);
                    mma_bf16(acc[mi][ni], ah[mi][0], ah[mi][1], ah[mi][2], ah[mi][3],
                             bl[nj][s2], bl[nj][s2 + 1]);
                    mma_bf16(acc[mi][ni], al[mi][0], al[mi][1], al[mi][2], al[mi][3],
                             bh[nj][s2], bh[nj][s2 + 1]);
                }
        }
        __syncthreads();
    }

    // epilogue
    int tr = lane >> 2, tc = (lane & 3) * 2;
#pragma unroll
    for (int mi = 0; mi < 2; mi++)
#pragma unroll
        for (int ni = 0; ni < 4; ni++) {
            int r = row0 + wm * 32 + mi * 16 + tr;
            int c = col0 + wn * 32 + ni * 8 + tc;
            if (r < M) {
                g_h1[(size_t)r * 256 + c]     = acc[mi][ni][0];
                g_h1[(size_t)r * 256 + c + 1] = acc[mi][ni][1];
            }
            if (r + 8 < M) {
                g_h1[(size_t)(r + 8) * 256 + c]     = acc[mi][ni][2];
                g_h1[(size_t)(r + 8) * 256 + c + 1] = acc[mi][ni][3];
            }
        }
}

// ---------------- attn1 ----------------
__global__ void k_attn1(const float* __restrict__ att_s, const float* __restrict__ att_d, int M) {
    int w = (blockIdx.x * blockDim.x + threadIdx.x) >> 5;
    int lane = threadIdx.x & 31;
    if (w >= M) return;
    int c0 = lane * 8;
    const float4* hp = (const float4*)&g_h1[(size_t)w * 256 + c0];
    float4 h0 = hp[0], h1v = hp[1];
    const float4* sp = (const float4*)&att_s[c0];
    const float4* dp = (const float4*)&att_d[c0];
    float4 s0 = sp[0], s1 = sp[1];
    float4 d0 = dp[0], d1 = dp[1];
    float ps = h0.x*s0.x + h0.y*s0.y + h0.z*s0.z + h0.w*s0.w
             + h1v.x*s1.x + h1v.y*s1.y + h1v.z*s1.z + h1v.w*s1.w;
    float pd = h0.x*d0.x + h0.y*d0.y + h0.z*d0.z + h0.w*d0.w
             + h1v.x*d1.x + h1v.y*d1.y + h1v.z*d1.z + h1v.w*d1.w;
#pragma unroll
    for (int o = 4; o >= 1; o >>= 1) {
        ps += __shfl_xor_sync(0xffffffffu, ps, o);
        pd += __shfl_xor_sync(0xffffffffu, pd, o);
    }
    if ((lane & 7) == 0) {
        int hh = lane >> 3;
        g_as1[w * 4 + hh] = ps;
        g_ad1[w * 4 + hh] = pd;
    }
}

// ---------------- agg1 ----------------
__global__ void k_agg1(const float* __restrict__ bias, int M) {
    int w = (blockIdx.x * blockDim.x + threadIdx.x) >> 5;
    int lane = threadIdx.x & 31;
    if (w >= M) return;
    int start = g_off[w], end = g_off[w + 1];
    float4 ad = *(const float4*)&g_ad1[w * 4];

    float m0 = -1e30f, m1 = -1e30f, m2 = -1e30f, m3 = -1e30f;
    for (int j = start + lane; j < end; j += 32) {
        int s = g_csr[j];
        float4 as = *(const float4*)&g_as1[s * 4];
        float e0 = as.x + ad.x; e0 = e0 > 0.f ? e0 : 0.2f * e0; m0 = fmaxf(m0, e0);
        float e1 = as.y + ad.y; e1 = e1 > 0.f ? e1 : 0.2f * e1; m1 = fmaxf(m1, e1);
        float e2 = as.z + ad.z; e2 = e2 > 0.f ? e2 : 0.2f * e2; m2 = fmaxf(m2, e2);
        float e3 = as.w + ad.w; e3 = e3 > 0.f ? e3 : 0.2f * e3; m3 = fmaxf(m3, e3);
    }
#pragma unroll
    for (int o = 16; o >= 1; o >>= 1) {
        m0 = fmaxf(m0, __shfl_xor_sync(0xffffffffu, m0, o));
        m1 = fmaxf(m1, __shfl_xor_sync(0xffffffffu, m1, o));
        m2 = fmaxf(m2, __shfl_xor_sync(0xffffffffu, m2, o));
        m3 = fmaxf(m3, __shfl_xor_sync(0xffffffffu, m3, o));
    }
    int hh = lane >> 3;
    float mh  = (hh == 0) ? m0   : (hh == 1) ? m1   : (hh == 2) ? m2   : m3;
    float adh = (hh == 0) ? ad.x : (hh == 1) ? ad.y : (hh == 2) ? ad.z : ad.w;

    float acc[8] = {0.f, 0.f, 0.f, 0.f, 0.f, 0.f, 0.f, 0.f};
    float denom = 0.f;
    int c0 = lane * 8;
    for (int j = start; j < end; j++) {
        int s = g_csr[j];
        float e = g_as1[s * 4 + hh] + adh;
        e = e > 0.f ? e : 0.2f * e;
        float wgt = __expf(e - mh);
        denom += wgt;
        const float4* hp = (const float4*)&g_h1[(size_t)s * 256 + c0];
        float4 v0 = hp[0], v1 = hp[1];
        acc[0] = fmaf(wgt, v0.x, acc[0]);
        acc[1] = fmaf(wgt, v0.y, acc[1]);
        acc[2] = fmaf(wgt, v0.z, acc[2]);
        acc[3] = fmaf(wgt, v0.w, acc[3]);
        acc[4] = fmaf(wgt, v1.x, acc[4]);
        acc[5] = fmaf(wgt, v1.y, acc[5]);
        acc[6] = fmaf(wgt, v1.z, acc[6]);
        acc[7] = fmaf(wgt, v1.w, acc[7]);
    }
    float inv = 1.f / denom;
#pragma unroll
    for (int k = 0; k < 8; k++) {
        float v = acc[k] * inv + bias[c0 + k];
        v = v > 0.f ? v : (__expf(v) - 1.f);   // ELU
        g_h1a[(size_t)w * 256 + c0 + k] = v;
    }
}

// ---------------- GEMM2: h2 = h1a @ W2  (M x 256 x 40) ----------------
__global__ void k_gemm2(const float* __restrict__ W2, int M) {
    __shared__ float Ws[256 * 40];
    int tid = threadIdx.x;               // 320 threads
    for (int i = tid; i < 256 * 40; i += 320) Ws[i] = W2[i];
    __syncthreads();
    int r = tid / 40, c = tid % 40;
    int gr = blockIdx.x * 8 + r;
    if (gr >= M) return;
    const float* hrow = &g_h1a[(size_t)gr * 256];
    float a0 = 0.f, a1 = 0.f, a2 = 0.f, a3 = 0.f;
#pragma unroll 4
    for (int k = 0; k < 256; k += 4) {
        a0 = fmaf(__ldg(&hrow[k + 0]), Ws[(k + 0) * 40 + c], a0);
        a1 = fmaf(__ldg(&hrow[k + 1]), Ws[(k + 1) * 40 + c], a1);
        a2 = fmaf(__ldg(&hrow[k + 2]), Ws[(k + 2) * 40 + c], a2);
        a3 = fmaf(__ldg(&hrow[k + 3]), Ws[(k + 3) * 40 + c], a3);
    }
    g_h2[(size_t)gr * 40 + c] = (a0 + a1) + (a2 + a3);
}

// ---------------- attn2 ----------------
__global__ void k_attn2(const float* __restrict__ att_s, const float* __restrict__ att_d, int M) {
    int w = (blockIdx.x * blockDim.x + threadIdx.x) >> 5;
    int lane = threadIdx.x & 31;
    if (w >= M) return;
    const float* h = &g_h2[(size_t)w * 40];
    float ps = h[lane] * __ldg(&att_s[lane]);
    float pd = h[lane] * __ldg(&att_d[lane]);
    if (lane < 8) {
        ps += h[32 + lane] * __ldg(&att_s[32 + lane]);
        pd += h[32 + lane] * __ldg(&att_d[32 + lane]);
    }
#pragma unroll
    for (int o = 16; o >= 1; o >>= 1) {
        ps += __shfl_xor_sync(0xffffffffu, ps, o);
        pd += __shfl_xor_sync(0xffffffffu, pd, o);
    }
    if (lane == 0) { g_as2[w] = ps; g_ad2[w] = pd; }
}

// ---------------- agg2: final output ----------------
__global__ void k_agg2(const float* __restrict__ b2, float* __restrict__ out, int M) {
    int w = (blockIdx.x * blockDim.x + threadIdx.x) >> 5;
    int lane = threadIdx.x & 31;
    if (w >= M) return;
    int start = g_off[w], end = g_off[w + 1];
    float adv = g_ad2[w];
    float m = -1e30f;
    for (int j = start + lane; j < end; j += 32) {
        int s = g_csr[j];
        float e = g_as2[s] + adv;
        e = e > 0.f ? e : 0.2f * e;
        m = fmaxf(m, e);
    }
#pragma unroll
    for (int o = 16; o >= 1; o >>= 1) m = fmaxf(m, __shfl_xor_sync(0xffffffffu, m, o));
    float denom = 0.f, acc0 = 0.f, acc1 = 0.f;
    for (int j = start; j < end; j++) {
        int s = g_csr[j];
        float e = g_as2[s] + adv;
        e = e > 0.f ? e : 0.2f * e;
        float wgt = __expf(e - m);
        denom += wgt;
        acc0 = fmaf(wgt, g_h2[(size_t)s * 40 + lane], acc0);
        if (lane < 8) acc1 = fmaf(wgt, g_h2[(size_t)s * 40 + 32 + lane], acc1);
    }
    float inv = 1.f / denom;
    out[(size_t)w * 40 + lane] = acc0 * inv + __ldg(&b2[lane]);
    if (lane < 8) out[(size_t)w * 40 + 32 + lane] = acc1 * inv + __ldg(&b2[32 + lane]);
}

// ---------------- launch ----------------
extern "C" void kernel_launch(void* const* d_in, const int* in_sizes, int n_in,
                              void* d_out, int out_size) {
    const float* x    = (const float*)d_in[0];
    const void*  edge = (const void*)d_in[1];
    const float* W1   = (const float*)d_in[2];
    const float* as1  = (const float*)d_in[3];
    const float* ad1  = (const float*)d_in[4];
    const float* b1   = (const float*)d_in[5];
    const float* W2   = (const float*)d_in[6];
    const float* as2  = (const float*)d_in[7];
    const float* ad2  = (const float*)d_in[8];
    const float* b2   = (const float*)d_in[9];
    float* out = (float*)d_out;

    int N  = in_sizes[0] / 256;
    int E  = in_sizes[1] / 2;
    int ET = E + N;
    int nb = (N + SCAN_B - 1) / SCAN_B;

    // Edge dtype detection
    k_detect<<<1, 32>>>((const int*)edge, E);

    // bf16 split of X and W1 (for tensor-core GEMM1)
    __nv_bfloat16 *xh, *xl, *wh, *wl;
    cudaGetSymbolAddress((void**)&xh, g_xh);
    cudaGetSymbolAddress((void**)&xl, g_xl);
    cudaGetSymbolAddress((void**)&wh, g_wh);
    cudaGetSymbolAddress((void**)&wl, g_wl);
    int nx = N * 256;
    k_split<<<(nx + 255) / 256, 256>>>(x, xh, xl, nx);
    k_split<<<(65536 + 255) / 256, 256>>>(W1, wh, wl, 65536);

    // CSR build (by destination)
    k_zero_deg<<<(N + 255) / 256, 256>>>(N);
    k_count<<<(ET + 255) / 256, 256>>>(edge, E, N);
    k_scan1<<<nb, SCAN_B>>>(N);
    k_scan2<<<1, 32>>>(nb, N);
    k_scan3<<<nb, SCAN_B>>>(N);
    k_scatter<<<(ET + 255) / 256, 256>>>(edge, E, N);

    // Layer 1
    dim3 g1(256 / 64, (N + 127) / 128);
    k_gemm1_tc<<<g1, 256>>>(N);
    int warpGrid = (N * 32 + 255) / 256;
    k_attn1<<<warpGrid, 256>>>(as1, ad1, N);
    k_agg1<<<warpGrid, 256>>>(b1, N);

    // Layer 2
    k_gemm2<<<(N + 7) / 8, 320>>>(W2, N);
    k_attn2<<<warpGrid, 256>>>(as2, ad2, N);
    k_agg2<<<warpGrid, 256>>>(b2, out, N);
}